// round 15
// baseline (speedup 1.0000x reference)
#include <cuda_runtime.h>
#include <cstdint>

#define SEQ  4096
#define NQ   64
#define DH   128
#define BMAX 16
#define SCALE 0.088388347648318447f
#define P 136
#define TILE_U (32*P)
#define NCH (SEQ/32)
#define DSMEM ((6*TILE_U + 2*SEQ)*4)

__device__ float g_Kr[(size_t)BMAX*SEQ*DH];
__device__ float g_Vr[(size_t)BMAX*SEQ*DH];

__device__ __forceinline__ float tf32r(float x) {
    uint32_t r;
    asm("cvt.rna.tf32.f32 %0, %1;" : "=r"(r) : "f"(x));
    return __uint_as_float(r);
}
__device__ __forceinline__ void mma_tf32(float* d, const uint32_t* a,
                                         uint32_t b0, uint32_t b1) {
    asm volatile(
        "mma.sync.aligned.m16n8k8.row.col.f32.tf32.tf32.f32 "
        "{%0,%1,%2,%3}, {%4,%5,%6,%7}, {%8,%9}, {%0,%1,%2,%3};"
        : "+f"(d[0]), "+f"(d[1]), "+f"(d[2]), "+f"(d[3])
        : "r"(a[0]), "r"(a[1]), "r"(a[2]), "r"(a[3]), "r"(b0), "r"(b1));
}
__device__ __forceinline__ void cpa16(uint32_t dst, const void* src) {
    asm volatile("cp.async.ca.shared.global [%0], [%1], 16;" :: "r"(dst), "l"(src));
}
#define CPA_COMMIT() asm volatile("cp.async.commit_group;" ::: "memory")
#define CPA_WAIT0()  asm volatile("cp.async.wait_group 0;" ::: "memory")

__global__ void prep_kernel(const float* __restrict__ K, const float* __restrict__ V,
                            int total4) {
    int i = blockIdx.x * blockDim.x + threadIdx.x;
    if (i >= total4) return;
    float4 k = ((const float4*)K)[i];
    float4 v = ((const float4*)V)[i];
    ((float4*)g_Kr)[i] = make_float4(tf32r(k.x), tf32r(k.y), tf32r(k.z), tf32r(k.w));
    ((float4*)g_Vr)[i] = make_float4(tf32r(v.x), tf32r(v.y), tf32r(v.z), tf32r(v.w));
}

// smem tiles: [K0][K1][Wq0u0][Wq0u1][Wq1u0][Wq1u1][a_s: 2*SEQ]
__global__ __launch_bounds__(512, 1)
void jac_tc(const float* __restrict__ Q, const float* __restrict__ K,
            float* __restrict__ out)
{
    extern __shared__ uint32_t sm[];
    float* a_s = (float*)(sm + 6*TILE_U);     // [2][SEQ]
    __shared__ float q_sm[2][DH], o_sm[2][DH], w_sm[2][DH], red_sm[16];

    const int tid = threadIdx.x, lane = tid & 31, wid = tid >> 5;
    const int qp = blockIdx.x, b = blockIdx.y;
    const int qsel = wid >> 3;                 // this warp's q (0/1)
    const float* __restrict__ Kb = K + (size_t)b * SEQ * DH;

    if (tid < 64) {
        int gq = tid >> 5, e = tid & 31;
        ((float4*)q_sm[gq])[e] =
            ((const float4*)(Q + ((size_t)b*NQ + qp*2 + gq)*DH))[e];
    }
    __syncthreads();

    // ---- Phase 1: scores (8 warps per q) ----
    {
        float4 qf = ((const float4*)q_sm[qsel])[lane];
        float lmax = -1e30f;
        for (int n = (wid & 7); n < SEQ; n += 8) {
            float4 kf = ((const float4*)(Kb + (size_t)n*DH))[lane];
            float dp = qf.x*kf.x + qf.y*kf.y + qf.z*kf.z + qf.w*kf.w;
            dp += __shfl_xor_sync(~0u, dp, 16); dp += __shfl_xor_sync(~0u, dp, 8);
            dp += __shfl_xor_sync(~0u, dp, 4);  dp += __shfl_xor_sync(~0u, dp, 2);
            dp += __shfl_xor_sync(~0u, dp, 1);
            dp *= SCALE;
            if (lane == 0) a_s[qsel*SEQ + n] = dp;
            lmax = fmaxf(lmax, dp);
        }
        if (lane == 0) red_sm[wid] = lmax;
    }
    __syncthreads();
    float gmax = red_sm[qsel*8];
    #pragma unroll
    for (int i = 1; i < 8; i++) gmax = fmaxf(gmax, red_sm[qsel*8 + i]);
    __syncthreads();

    // ---- Phase 2: softmax (256 threads per q) ----
    {
        const int t8 = tid & 255;
        float* aq = a_s + qsel*SEQ;
        float lsum = 0.f;
        for (int n = t8; n < SEQ; n += 256) {
            float e = __expf(aq[n] - gmax); aq[n] = e; lsum += e;
        }
        lsum += __shfl_xor_sync(~0u, lsum, 16); lsum += __shfl_xor_sync(~0u, lsum, 8);
        lsum += __shfl_xor_sync(~0u, lsum, 4);  lsum += __shfl_xor_sync(~0u, lsum, 2);
        lsum += __shfl_xor_sync(~0u, lsum, 1);
        if (lane == 0) red_sm[wid] = lsum;
        __syncthreads();
        float gsum = 0.f;
        #pragma unroll
        for (int i = 0; i < 8; i++) gsum += red_sm[qsel*8 + i];
        const float inv = 1.0f / gsum;
        for (int n = t8; n < SEQ; n += 256) aq[n] *= inv;
    }
    __syncthreads();

    // ---- Phase 3: q-pair shared-K/V tf32 mma ----
    const float* Krb = g_Kr + (size_t)b*SEQ*DH;
    const float* Vrb = g_Vr + (size_t)b*SEQ*DH;
    const int sn = tid >> 4, sc = (tid & 15) * 8;   // 32 rows x 16x8 cols
    const int g = lane >> 2, ti = lane & 3;
    const int cw = wid & 7;
    const int v0 = (cw & 1) * 64, k0 = (cw >> 1) * 32;
    const uint32_t ksa = (uint32_t)__cvta_generic_to_shared(sm);

    float pov[2][8], pwv[2][8];
    #pragma unroll
    for (int qq = 0; qq < 2; qq++)
        #pragma unroll
        for (int j = 0; j < 8; j++) { pov[qq][j] = 0.f; pwv[qq][j] = 0.f; }
    float acc[4][4][4];
    #pragma unroll
    for (int mi = 0; mi < 4; mi++)
        #pragma unroll
        for (int nj = 0; nj < 4; nj++)
            #pragma unroll
            for (int e = 0; e < 4; e++) acc[mi][nj][e] = 0.f;

    for (int ch = 0; ch < NCH; ch += 2) {
        const int n0 = ch * 32;
        // K tiles via cp.async (shared by both q)
        #pragma unroll
        for (int u = 0; u < 2; u++) {
            uint32_t kd = ksa + (uint32_t)(u*TILE_U + sn*P + sc) * 4;
            const float* ks = Krb + (size_t)(n0 + u*32 + sn)*DH + sc;
            cpa16(kd, ks);  cpa16(kd + 16, ks + 4);
        }
        CPA_COMMIT();
        // W tiles for both q from one V read
        #pragma unroll
        for (int u = 0; u < 2; u++) {
            const int nn = n0 + u*32;
            const float a0 = a_s[nn + sn];
            const float a1 = a_s[SEQ + nn + sn];
            const float4* vr = (const float4*)(Vrb + (size_t)(nn+sn)*DH + sc);
            uint32_t* wd0 = sm + (2+u)*TILE_U + sn*P + sc;   // q0
            uint32_t* wd1 = sm + (4+u)*TILE_U + sn*P + sc;   // q1
            #pragma unroll
            for (int j = 0; j < 2; j++) {
                float4 vv = vr[j];
                float4 w0 = make_float4(a0*vv.x, a0*vv.y, a0*vv.z, a0*vv.w);
                float4 w1 = make_float4(a1*vv.x, a1*vv.y, a1*vv.z, a1*vv.w);
                pov[0][4*j  ] += w0.x;  pov[0][4*j+1] += w0.y;
                pov[0][4*j+2] += w0.z;  pov[0][4*j+3] += w0.w;
                pov[1][4*j  ] += w1.x;  pov[1][4*j+1] += w1.y;
                pov[1][4*j+2] += w1.z;  pov[1][4*j+3] += w1.w;
                *(uint4*)(wd0 + 4*j) = make_uint4(
                    __float_as_uint(w0.x)+0x1000u, __float_as_uint(w0.y)+0x1000u,
                    __float_as_uint(w0.z)+0x1000u, __float_as_uint(w0.w)+0x1000u);
                *(uint4*)(wd1 + 4*j) = make_uint4(
                    __float_as_uint(w1.x)+0x1000u, __float_as_uint(w1.y)+0x1000u,
                    __float_as_uint(w1.z)+0x1000u, __float_as_uint(w1.w)+0x1000u);
            }
        }
        CPA_WAIT0();
        __syncthreads();
        // MMA: 8 warps per q, 64x32 tiles (HW-verified mapping)
        #pragma unroll
        for (int u = 0; u < 2; u++) {
            const uint32_t* Kc = sm + u*TILE_U;
            const uint32_t* Wc = sm + (2 + qsel*2 + u)*TILE_U;
            #pragma unroll
            for (int s = 0; s < 4; s++) {
                const uint32_t* Wr0 = Wc + (s*8 + ti)*P;
                const uint32_t* Wr4 = Wr0 + 4*P;
                uint32_t af[4][4];
                #pragma unroll
                for (int mi = 0; mi < 4; mi++) {
                    int cbv = v0 + mi*16 + g;
                    af[mi][0] = Wr0[cbv];   af[mi][1] = Wr0[cbv+8];
                    af[mi][2] = Wr4[cbv];   af[mi][3] = Wr4[cbv+8];
                }
                const uint32_t* Kr0 = Kc + (s*8 + ti)*P;
                const uint32_t* Kr4 = Kr0 + 4*P;
                #pragma unroll
                for (int nj = 0; nj < 4; nj++) {
                    int cbk = k0 + nj*8 + g;
                    uint32_t b0 = Kr0[cbk], b1 = Kr4[cbk];
                    #pragma unroll
                    for (int mi = 0; mi < 4; mi++)
                        mma_tf32(acc[mi][nj], af[mi], b0, b1);
                }
            }
        }
        // w partials for both q from resident K tiles (read once)
        #pragma unroll
        for (int u = 0; u < 2; u++) {
            const int nn = n0 + u*32;
            const float a0 = a_s[nn + sn];
            const float a1 = a_s[SEQ + nn + sn];
            const uint32_t* Ks = sm + u*TILE_U + sn*P + sc;
            #pragma unroll
            for (int j = 0; j < 2; j++) {
                uint4 ka = *(const uint4*)(Ks + 4*j);
                float kx = __uint_as_float(ka.x), ky = __uint_as_float(ka.y);
                float kz = __uint_as_float(ka.z), kw = __uint_as_float(ka.w);
                pwv[0][4*j  ] += a0*kx;  pwv[0][4*j+1] += a0*ky;
                pwv[0][4*j+2] += a0*kz;  pwv[0][4*j+3] += a0*kw;
                pwv[1][4*j  ] += a1*kx;  pwv[1][4*j+1] += a1*ky;
                pwv[1][4*j+2] += a1*kz;  pwv[1][4*j+3] += a1*kw;
            }
        }
        __syncthreads();
    }

    // ---- reduce o/w partials (reuse 4 tiles; [32][128] each) ----
    #pragma unroll
    for (int qq = 0; qq < 2; qq++) {
        float* op = (float*)(sm + (qq*2    )*TILE_U);
        float* wp = (float*)(sm + (qq*2 + 1)*TILE_U);
        #pragma unroll
        for (int j = 0; j < 8; j++) {
            op[sn*DH + sc + j] = pov[qq][j];
            wp[sn*DH + sc + j] = pwv[qq][j];
        }
    }
    __syncthreads();
    {
        const int sel = tid >> 7;       // 0..3: o_q0, w_q0, o_q1, w_q1
        const int t7 = tid & 127;
        const float* src = (const float*)(sm + sel*TILE_U);
        float s = 0.f;
        #pragma unroll
        for (int n = 0; n < 32; n++) s += src[n*DH + t7];
        if (sel == 0)      o_sm[0][t7] = s;
        else if (sel == 1) w_sm[0][t7] = s;
        else if (sel == 2) o_sm[1][t7] = s;
        else               w_sm[1][t7] = s;
    }
    __syncthreads();

    // ---- epilogue ----
    float* ob = out + (((size_t)b*NQ + qp*2 + qsel)) * DH * DH;
    #pragma unroll
    for (int mi = 0; mi < 4; mi++) {
        int vr = v0 + mi*16 + g;
        float ov1 = o_sm[qsel][vr], ov2 = o_sm[qsel][vr + 8];
        #pragma unroll
        for (int nj = 0; nj < 4; nj++) {
            int kc = k0 + nj*8 + ti*2;
            float w1 = w_sm[qsel][kc], w2 = w_sm[qsel][kc+1];
            float2 r1 = make_float2(SCALE*(acc[mi][nj][0] - ov1*w1),
                                    SCALE*(acc[mi][nj][1] - ov1*w2));
            float2 r2 = make_float2(SCALE*(acc[mi][nj][2] - ov2*w1),
                                    SCALE*(acc[mi][nj][3] - ov2*w2));
            *(float2*)(ob + (size_t)vr*DH + kc)     = r1;
            *(float2*)(ob + (size_t)(vr+8)*DH + kc) = r2;
        }
    }
}

extern "C" void kernel_launch(void* const* d_in, const int* in_sizes, int n_in,
                              void* d_out, int out_size) {
    const float* Q = (const float*)d_in[0];
    const float* K = (const float*)d_in[1];
    const float* V = (const float*)d_in[2];
    float* out = (float*)d_out;
    int batch = in_sizes[1] / (SEQ * DH);
    int total4 = batch * SEQ * DH / 4;
    prep_kernel<<<(total4 + 255)/256, 256>>>(K, V, total4);
    cudaFuncSetAttribute(jac_tc, cudaFuncAttributeMaxDynamicSharedMemorySize, DSMEM);
    jac_tc<<<dim3(NQ/2, batch), 512, DSMEM>>>(Q, K, out);
}

// round 16
// speedup vs baseline: 1.0712x; 1.0712x over previous
#include <cuda_runtime.h>
#include <cstdint>

#define SEQ  4096
#define NQ   64
#define DH   128
#define BMAX 16
#define SCALE 0.088388347648318447f
#define TW   4096                 // tile words: 32 rows x 128 cols
#define NCH  (SEQ/32)
#define DSMEM ((4*TW + SEQ)*4)    // K[2] V[2] + a_s = 80 KB

__device__ float g_Kr[(size_t)BMAX*SEQ*DH];
__device__ float g_Vr[(size_t)BMAX*SEQ*DH];

__device__ __forceinline__ float tf32r(float x) {
    uint32_t r;
    asm("cvt.rna.tf32.f32 %0, %1;" : "=r"(r) : "f"(x));
    return __uint_as_float(r);
}
__device__ __forceinline__ void mma_tf32(float* d, const uint32_t* a,
                                         uint32_t b0, uint32_t b1) {
    asm volatile(
        "mma.sync.aligned.m16n8k8.row.col.f32.tf32.tf32.f32 "
        "{%0,%1,%2,%3}, {%4,%5,%6,%7}, {%8,%9}, {%0,%1,%2,%3};"
        : "+f"(d[0]), "+f"(d[1]), "+f"(d[2]), "+f"(d[3])
        : "r"(a[0]), "r"(a[1]), "r"(a[2]), "r"(a[3]), "r"(b0), "r"(b1));
}
__device__ __forceinline__ void cpa16(uint32_t dst, const void* src) {
    asm volatile("cp.async.ca.shared.global [%0], [%1], 16;" :: "r"(dst), "l"(src));
}
#define CPA_COMMIT() asm volatile("cp.async.commit_group;" ::: "memory")
#define CPA_WAIT1()  asm volatile("cp.async.wait_group 1;" ::: "memory")
__device__ __forceinline__ uint32_t rnt(float x) {           // fp32 -> tf32 RN bits
    return __float_as_uint(x) + 0x1000u;
}

__global__ void prep_kernel(const float* __restrict__ K, const float* __restrict__ V,
                            int total4) {
    int i = blockIdx.x * blockDim.x + threadIdx.x;
    if (i >= total4) return;
    float4 k = ((const float4*)K)[i];
    float4 v = ((const float4*)V)[i];
    ((float4*)g_Kr)[i] = make_float4(tf32r(k.x), tf32r(k.y), tf32r(k.z), tf32r(k.w));
    ((float4*)g_Vr)[i] = make_float4(tf32r(v.x), tf32r(v.y), tf32r(v.z), tf32r(v.w));
}

// smem: [K0][K1][V0][V1][a_s]; tiles pitch 128 words, XOR swizzle col ^ 8*(row&3)
__global__ __launch_bounds__(256, 2)
void jac_tc(const float* __restrict__ Q, const float* __restrict__ K,
            float* __restrict__ out)
{
    extern __shared__ uint32_t sm[];
    float* a_s = (float*)(sm + 4*TW);
    __shared__ float q_sm[DH], o_sm[DH], w_sm[DH], red_sm[8];

    const int tid = threadIdx.x, lane = tid & 31, wid = tid >> 5;
    const int q = blockIdx.x, b = blockIdx.y;
    const float* __restrict__ Kb = K + (size_t)b * SEQ * DH;

    if (tid < 32) ((float4*)q_sm)[tid] =
        ((const float4*)(Q + ((size_t)b*NQ + q)*DH))[tid];
    __syncthreads();

    // ---- Phase 1: scores ----
    float4 qf = ((const float4*)q_sm)[lane];
    float lmax = -1e30f;
    for (int n = wid; n < SEQ; n += 8) {
        float4 kf = ((const float4*)(Kb + (size_t)n*DH))[lane];
        float dp = qf.x*kf.x + qf.y*kf.y + qf.z*kf.z + qf.w*kf.w;
        dp += __shfl_xor_sync(~0u, dp, 16); dp += __shfl_xor_sync(~0u, dp, 8);
        dp += __shfl_xor_sync(~0u, dp, 4);  dp += __shfl_xor_sync(~0u, dp, 2);
        dp += __shfl_xor_sync(~0u, dp, 1);
        dp *= SCALE;
        if (lane == 0) a_s[n] = dp;
        lmax = fmaxf(lmax, dp);
    }
    if (lane == 0) red_sm[wid] = lmax;
    __syncthreads();
    float gmax = red_sm[0];
    #pragma unroll
    for (int i = 1; i < 8; i++) gmax = fmaxf(gmax, red_sm[i]);
    __syncthreads();

    // ---- Phase 2: softmax ----
    float lsum = 0.f;
    for (int n = tid; n < SEQ; n += 256) {
        float e = __expf(a_s[n] - gmax); a_s[n] = e; lsum += e;
    }
    lsum += __shfl_xor_sync(~0u, lsum, 16); lsum += __shfl_xor_sync(~0u, lsum, 8);
    lsum += __shfl_xor_sync(~0u, lsum, 4);  lsum += __shfl_xor_sync(~0u, lsum, 2);
    lsum += __shfl_xor_sync(~0u, lsum, 1);
    if (lane == 0) red_sm[wid] = lsum;
    __syncthreads();
    float gsum = 0.f;
    #pragma unroll
    for (int i = 0; i < 8; i++) gsum += red_sm[i];
    const float inv = 1.0f / gsum;
    for (int n = tid; n < SEQ; n += 256) a_s[n] *= inv;
    __syncthreads();

    // ---- Phase 3: fully-async staged tf32 mma ----
    const float* Krb = g_Kr + (size_t)b*SEQ*DH;
    const float* Vrb = g_Vr + (size_t)b*SEQ*DH;
    const int sn = tid >> 4, sc = (tid & 15) * 8;       // rows sn, sn+16; 8 cols
    const int g = lane >> 2, ti = lane & 3;
    const int v0 = (wid & 1) * 64, k0 = (wid >> 1) * 32;
    const int xo  = ti * 8;                              // frag-row swizzle
    const int xo2 = (sn & 3) * 8;                        // staging-row swizzle
    const uint32_t ksa = (uint32_t)__cvta_generic_to_shared(sm);
    const uint32_t vsa = ksa + 2*TW*4;

    float pov[8], pwv[8];
    #pragma unroll
    for (int j = 0; j < 8; j++) { pov[j] = 0.f; pwv[j] = 0.f; }
    float acc[4][4][4];
    #pragma unroll
    for (int mi = 0; mi < 4; mi++)
        #pragma unroll
        for (int nj = 0; nj < 4; nj++)
            #pragma unroll
            for (int e = 0; e < 4; e++) acc[mi][nj][e] = 0.f;

    // cp.async one chunk (K+V tiles) into ring slot ch&1
    #define ISSUE(ch_) do {                                                   \
        int _c = (ch_) < NCH ? (ch_) : 0;                                     \
        uint32_t _sl = ((uint32_t)(ch_)) & 1u;                                \
        const int _n0 = _c * 32;                                              \
        uint32_t _o0 = (_sl*TW + (uint32_t)(sn*128      + (sc ^ xo2))) * 4;   \
        uint32_t _o1 = (_sl*TW + (uint32_t)((sn+16)*128 + (sc ^ xo2))) * 4;   \
        const float* _k0 = Krb + (size_t)(_n0+sn)*DH + sc;                    \
        const float* _k1 = Krb + (size_t)(_n0+sn+16)*DH + sc;                 \
        const float* _v0 = Vrb + (size_t)(_n0+sn)*DH + sc;                    \
        const float* _v1 = Vrb + (size_t)(_n0+sn+16)*DH + sc;                 \
        cpa16(ksa + _o0, _k0);       cpa16(ksa + _o0 + 16, _k0 + 4);          \
        cpa16(ksa + _o1, _k1);       cpa16(ksa + _o1 + 16, _k1 + 4);          \
        cpa16(vsa + _o0, _v0);       cpa16(vsa + _o0 + 16, _v0 + 4);          \
        cpa16(vsa + _o1, _v1);       cpa16(vsa + _o1 + 16, _v1 + 4);          \
        CPA_COMMIT();                                                         \
    } while (0)

    ISSUE(0);
    for (int ch = 0; ch < NCH; ch++) {
        ISSUE(ch + 1);
        CPA_WAIT1();
        __syncthreads();
        const int slot = ch & 1, n0 = ch * 32;
        const uint32_t* Kc = sm + slot*TW;
        const float*    Vc = (const float*)(sm + (2+slot)*TW);

        #pragma unroll
        for (int s = 0; s < 4; s++) {
            const int n = s*8 + ti;
            const float a0 = a_s[n0 + n];
            const float a1 = a_s[n0 + n + 4];
            const float* Vr0 = Vc + n*128;
            const float* Vr4 = Vr0 + 512;
            uint32_t af[4][4];
            #pragma unroll
            for (int mi = 0; mi < 4; mi++) {
                int c0 = (v0 + mi*16 + g) ^ xo;
                int c1 = (v0 + mi*16 + g + 8) ^ xo;
                af[mi][0] = rnt(a0 * Vr0[c0]);
                af[mi][1] = rnt(a0 * Vr0[c1]);
                af[mi][2] = rnt(a1 * Vr4[c0]);
                af[mi][3] = rnt(a1 * Vr4[c1]);
            }
            const uint32_t* Kr0 = Kc + n*128;
            const uint32_t* Kr4 = Kr0 + 512;
            #pragma unroll
            for (int nj = 0; nj < 4; nj++) {
                int cb = (k0 + nj*8 + g) ^ xo;
                uint32_t b0 = Kr0[cb], b1 = Kr4[cb];
                #pragma unroll
                for (int mi = 0; mi < 4; mi++)
                    mma_tf32(acc[mi][nj], af[mi], b0, b1);
            }
        }
        // rank-1 partials from resident tiles
        {
            const float a0 = a_s[n0 + sn];
            const float a1 = a_s[n0 + sn + 16];
            const float* Vp0 = Vc + sn*128 + (sc ^ xo2);
            const float* Vp1 = Vp0 + 16*128;
            const float* Kp0 = (const float*)Kc + sn*128 + (sc ^ xo2);
            const float* Kp1 = Kp0 + 16*128;
            #pragma unroll
            for (int j = 0; j < 2; j++) {
                float4 va = ((const float4*)Vp0)[j], vb = ((const float4*)Vp1)[j];
                float4 ka = ((const float4*)Kp0)[j], kb = ((const float4*)Kp1)[j];
                pov[4*j  ] += a0*va.x + a1*vb.x;  pov[4*j+1] += a0*va.y + a1*vb.y;
                pov[4*j+2] += a0*va.z + a1*vb.z;  pov[4*j+3] += a0*va.w + a1*vb.w;
                pwv[4*j  ] += a0*ka.x + a1*kb.x;  pwv[4*j+1] += a0*ka.y + a1*kb.y;
                pwv[4*j+2] += a0*ka.z + a1*kb.z;  pwv[4*j+3] += a0*ka.w + a1*kb.w;
            }
        }
        __syncthreads();
    }

    // ---- reduce o/w partials (reuse tiles; [16][128] each) ----
    float* opart = (float*)sm;
    float* wpart = (float*)(sm + TW);
    #pragma unroll
    for (int j = 0; j < 8; j++) {
        opart[sn*DH + sc + j] = pov[j];
        wpart[sn*DH + sc + j] = pwv[j];
    }
    __syncthreads();
    if (tid < DH) {
        float s = 0.f;
        #pragma unroll
        for (int n = 0; n < 16; n++) s += opart[n*DH + tid];
        o_sm[tid] = s;
    } else {
        int t = tid - DH;
        float s = 0.f;
        #pragma unroll
        for (int n = 0; n < 16; n++) s += wpart[n*DH + t];
        w_sm[t] = s;
    }
    __syncthreads();

    // ---- epilogue ----
    float* ob = out + ((size_t)b*NQ + q) * DH * DH;
    #pragma unroll
    for (int mi = 0; mi < 4; mi++) {
        int vr = v0 + mi*16 + g;
        float ov1 = o_sm[vr], ov2 = o_sm[vr + 8];
        #pragma unroll
        for (int nj = 0; nj < 4; nj++) {
            int kc = k0 + nj*8 + ti*2;
            float w1 = w_sm[kc], w2 = w_sm[kc+1];
            float2 r1 = make_float2(SCALE*(acc[mi][nj][0] - ov1*w1),
                                    SCALE*(acc[mi][nj][1] - ov1*w2));
            float2 r2 = make_float2(SCALE*(acc[mi][nj][2] - ov2*w1),
                                    SCALE*(acc[mi][nj][3] - ov2*w2));
            *(float2*)(ob + (size_t)vr*DH + kc)     = r1;
            *(float2*)(ob + (size_t)(vr+8)*DH + kc) = r2;
        }
    }
}

extern "C" void kernel_launch(void* const* d_in, const int* in_sizes, int n_in,
                              void* d_out, int out_size) {
    const float* Q = (const float*)d_in[0];
    const float* K = (const float*)d_in[1];
    const float* V = (const float*)d_in[2];
    float* out = (float*)d_out;
    int batch = in_sizes[1] / (SEQ * DH);
    int total4 = batch * SEQ * DH / 4;
    prep_kernel<<<(total4 + 255)/256, 256>>>(K, V, total4);
    cudaFuncSetAttribute(jac_tc, cudaFuncAttributeMaxDynamicSharedMemorySize, DSMEM);
    jac_tc<<<dim3(NQ, batch), 256, DSMEM>>>(Q, K, out);
}

// round 17
// speedup vs baseline: 1.3261x; 1.2380x over previous
#include <cuda_runtime.h>
#include <cuda_fp16.h>
#include <cstdint>

#define SEQ  4096
#define NQ   64
#define DH   128
#define BMAX 16
#define SCALE 0.088388347648318447f
#define PITCH 20                    // words per 32-n fp16 row (16 data + 4 pad)
#define TWH   (128*PITCH)           // words per tile (128 rows)
#define NCH   (SEQ/32)
// smem words: Kt[3] Vt[3] Wt[1] + a_s
#define DSMEM ((7*TWH + SEQ)*4)

__device__ __half g_Kth[(size_t)BMAX*DH*SEQ];   // K^T fp16 [b][d][n]
__device__ __half g_Vth[(size_t)BMAX*DH*SEQ];   // V^T fp16 [b][d][n]

__device__ __forceinline__ void mma_f16(float* d, const uint32_t* a,
                                        uint32_t b0, uint32_t b1) {
    asm volatile(
        "mma.sync.aligned.m16n8k16.row.col.f32.f16.f16.f32 "
        "{%0,%1,%2,%3}, {%4,%5,%6,%7}, {%8,%9}, {%0,%1,%2,%3};"
        : "+f"(d[0]), "+f"(d[1]), "+f"(d[2]), "+f"(d[3])
        : "r"(a[0]), "r"(a[1]), "r"(a[2]), "r"(a[3]), "r"(b0), "r"(b1));
}
__device__ __forceinline__ void cpa16(uint32_t dst, const void* src) {
    asm volatile("cp.async.ca.shared.global [%0], [%1], 16;" :: "r"(dst), "l"(src));
}
#define CPA_COMMIT() asm volatile("cp.async.commit_group;" ::: "memory")
#define CPA_WAIT1()  asm volatile("cp.async.wait_group 1;" ::: "memory")
#define CPA_WAIT0()  asm volatile("cp.async.wait_group 0;" ::: "memory")

// ---- prep: K,V -> transposed fp16 [b][d][n] ----
__global__ void prep_kernel(const float* __restrict__ K, const float* __restrict__ V) {
    __shared__ float t1[32][33], t2[32][33];
    int b = blockIdx.z, n0 = blockIdx.x*32, d0 = blockIdx.y*32;
    int tx = threadIdx.x, ty = threadIdx.y;
    const float* Kb = K + (size_t)b*SEQ*DH;
    const float* Vb = V + (size_t)b*SEQ*DH;
    for (int i = ty; i < 32; i += 8) {
        t1[i][tx] = Kb[(size_t)(n0+i)*DH + d0 + tx];
        t2[i][tx] = Vb[(size_t)(n0+i)*DH + d0 + tx];
    }
    __syncthreads();
    for (int i = ty; i < 32; i += 8) {
        size_t idx = ((size_t)b*DH + d0 + i)*SEQ + n0 + tx;
        g_Kth[idx] = __float2half_rn(t1[tx][i]);
        g_Vth[idx] = __float2half_rn(t2[tx][i]);
    }
}

// smem: [Kt0][Kt1][Kt2][Vt0][Vt1][Vt2][Wt][a_s]
__global__ __launch_bounds__(256, 2)
void jac_tc(const float* __restrict__ Q, const float* __restrict__ K,
            float* __restrict__ out)
{
    extern __shared__ uint32_t sm[];
    uint32_t* Wt  = sm + 6*TWH;
    float*    a_s = (float*)(sm + 7*TWH);
    __shared__ float q_sm[DH], o_sm[DH], w_sm[DH], red_sm[8];

    const int tid = threadIdx.x, lane = tid & 31, wid = tid >> 5;
    const int q = blockIdx.x, b = blockIdx.y;
    const float* __restrict__ Kb = K + (size_t)b * SEQ * DH;

    if (tid < 32) ((float4*)q_sm)[tid] =
        ((const float4*)(Q + ((size_t)b*NQ + q)*DH))[tid];
    __syncthreads();

    // ---- Phase 1: scores (exact fp32) ----
    float4 qf = ((const float4*)q_sm)[lane];
    float lmax = -1e30f;
    for (int n = wid; n < SEQ; n += 8) {
        float4 kf = ((const float4*)(Kb + (size_t)n*DH))[lane];
        float dp = qf.x*kf.x + qf.y*kf.y + qf.z*kf.z + qf.w*kf.w;
        dp += __shfl_xor_sync(~0u, dp, 16); dp += __shfl_xor_sync(~0u, dp, 8);
        dp += __shfl_xor_sync(~0u, dp, 4);  dp += __shfl_xor_sync(~0u, dp, 2);
        dp += __shfl_xor_sync(~0u, dp, 1);
        dp *= SCALE;
        if (lane == 0) a_s[n] = dp;
        lmax = fmaxf(lmax, dp);
    }
    if (lane == 0) red_sm[wid] = lmax;
    __syncthreads();
    float gmax = red_sm[0];
    #pragma unroll
    for (int i = 1; i < 8; i++) gmax = fmaxf(gmax, red_sm[i]);
    __syncthreads();

    // ---- Phase 2: softmax ----
    float lsum = 0.f;
    for (int n = tid; n < SEQ; n += 256) {
        float e = __expf(a_s[n] - gmax); a_s[n] = e; lsum += e;
    }
    lsum += __shfl_xor_sync(~0u, lsum, 16); lsum += __shfl_xor_sync(~0u, lsum, 8);
    lsum += __shfl_xor_sync(~0u, lsum, 4);  lsum += __shfl_xor_sync(~0u, lsum, 2);
    lsum += __shfl_xor_sync(~0u, lsum, 1);
    if (lane == 0) red_sm[wid] = lsum;
    __syncthreads();
    float gsum = 0.f;
    #pragma unroll
    for (int i = 0; i < 8; i++) gsum += red_sm[i];
    const float inv = 1.0f / gsum;
    for (int n = tid; n < SEQ; n += 256) a_s[n] *= inv;
    __syncthreads();

    // ---- Phase 3: fp16 m16n8k16, ring-3 cp.async ----
    const __half* Ktg = g_Kth + (size_t)b*DH*SEQ;
    const __half* Vtg = g_Vth + (size_t)b*DH*SEQ;
    const int g = lane >> 2, ti = lane & 3;
    const int v0 = (wid & 1) * 64, k0 = (wid >> 1) * 32;
    const int sv = tid >> 1, nh = tid & 1;            // staging: row, n-half
    const uint32_t sbase = (uint32_t)__cvta_generic_to_shared(sm);

    float povS = 0.f, pwvS = 0.f;
    float acc[4][4][4];
    #pragma unroll
    for (int mi = 0; mi < 4; mi++)
        #pragma unroll
        for (int nj = 0; nj < 4; nj++)
            #pragma unroll
            for (int e = 0; e < 4; e++) acc[mi][nj][e] = 0.f;

    #define ISSUE(ch_) do {                                                   \
        int _c = (ch_) < NCH ? (ch_) : 0;                                     \
        uint32_t _sl = ((uint32_t)(ch_)) % 3u;                                \
        uint32_t _wo = (uint32_t)(sv*PITCH + nh*8) * 4;                       \
        const __half* _ks = Ktg + (size_t)sv*SEQ + _c*32 + nh*16;             \
        const __half* _vs = Vtg + (size_t)sv*SEQ + _c*32 + nh*16;             \
        uint32_t _kd = sbase + _sl*(TWH*4) + _wo;                             \
        uint32_t _vd = sbase + (3+_sl)*(TWH*4) + _wo;                         \
        cpa16(_kd, _ks);  cpa16(_kd + 16, _ks + 8);                           \
        cpa16(_vd, _vs);  cpa16(_vd + 16, _vs + 8);                           \
        CPA_COMMIT();                                                         \
    } while (0)

    ISSUE(0);  ISSUE(1);
    for (int ch = 0; ch < NCH; ch++) {
        const int slot = ch % 3, n0 = ch * 32;
        CPA_WAIT1();
        __syncthreads();
        const uint32_t* Kc = sm + slot*TWH;
        const uint32_t* Vc = sm + (3+slot)*TWH;
        // stage Wt = fp16(a * V) + rank-1 partials (fp32 math)
        {
            float4 aa[4];
            #pragma unroll
            for (int j = 0; j < 4; j++)
                aa[j] = *(const float4*)(a_s + n0 + nh*16 + j*4);
            const float* av = (const float*)aa;
            uint4 vu0 = *(const uint4*)(Vc + sv*PITCH + nh*8);
            uint4 vu1 = *(const uint4*)(Vc + sv*PITCH + nh*8 + 4);
            uint4 ku0 = *(const uint4*)(Kc + sv*PITCH + nh*8);
            uint4 ku1 = *(const uint4*)(Kc + sv*PITCH + nh*8 + 4);
            const __half2* vh = (const __half2*)&vu0;   // 8 half2 total via both
            const __half2* kh = (const __half2*)&ku0;
            uint32_t wout[8];
            #pragma unroll
            for (int j = 0; j < 8; j++) {
                __half2 vv = (j < 4) ? vh[j] : ((const __half2*)&vu1)[j-4];
                __half2 kk = (j < 4) ? kh[j] : ((const __half2*)&ku1)[j-4];
                float2 vf = __half22float2(vv);
                float2 kf = __half22float2(kk);
                float a0 = av[2*j], a1 = av[2*j+1];
                float w0 = a0 * vf.x, w1 = a1 * vf.y;
                povS += w0 + w1;
                pwvS += a0 * kf.x + a1 * kf.y;
                __half2 wh = __floats2half2_rn(w0, w1);
                wout[j] = *(uint32_t*)&wh;
            }
            *(uint4*)(Wt + sv*PITCH + nh*8)     = make_uint4(wout[0], wout[1], wout[2], wout[3]);
            *(uint4*)(Wt + sv*PITCH + nh*8 + 4) = make_uint4(wout[4], wout[5], wout[6], wout[7]);
        }
        ISSUE(ch + 2);
        __syncthreads();
        // MMA: 8 warps, 64x32 tiles, fp16 k16 x2 steps
        #pragma unroll
        for (int s2 = 0; s2 < 2; s2++) {
            const int wb = s2*8 + ti;
            uint32_t af[4][4];
            #pragma unroll
            for (int mi = 0; mi < 4; mi++) {
                int r0 = (v0 + mi*16 + g) * PITCH;
                int r8 = r0 + 8*PITCH;
                af[mi][0] = Wt[r0 + wb];     af[mi][1] = Wt[r8 + wb];
                af[mi][2] = Wt[r0 + wb + 4]; af[mi][3] = Wt[r8 + wb + 4];
            }
            #pragma unroll
            for (int nj = 0; nj < 4; nj++) {
                int rk = (k0 + nj*8 + g) * PITCH;
                uint32_t b0 = Kc[rk + wb], b1 = Kc[rk + wb + 4];
                #pragma unroll
                for (int mi = 0; mi < 4; mi++)
                    mma_f16(acc[mi][nj], af[mi], b0, b1);
            }
        }
        __syncthreads();
    }
    CPA_WAIT0();
    __syncthreads();

    // ---- reduce o/w partials ----
    float* opart = (float*)sm;          // [256]
    float* wpart = (float*)sm + 256;
    opart[tid] = povS;
    wpart[tid] = pwvS;
    __syncthreads();
    if (tid < DH) {
        o_sm[tid] = opart[2*tid] + opart[2*tid+1];
    } else {
        int t = tid - DH;
        w_sm[t] = wpart[2*t] + wpart[2*t+1];
    }
    __syncthreads();

    // ---- epilogue ----
    float* ob = out + ((size_t)b*NQ + q) * DH * DH;
    #pragma unroll
    for (int mi = 0; mi < 4; mi++) {
        int vr = v0 + mi*16 + g;
        float ov1 = o_sm[vr], ov2 = o_sm[vr + 8];
        #pragma unroll
        for (int nj = 0; nj < 4; nj++) {
            int kc = k0 + nj*8 + ti*2;
            float w1 = w_sm[kc], w2 = w_sm[kc+1];
            float2 r1 = make_float2(SCALE*(acc[mi][nj][0] - ov1*w1),
                                    SCALE*(acc[mi][nj][1] - ov1*w2));
            float2 r2 = make_float2(SCALE*(acc[mi][nj][2] - ov2*w1),
                                    SCALE*(acc[mi][nj][3] - ov2*w2));
            *(float2*)(ob + (size_t)vr*DH + kc)     = r1;
            *(float2*)(ob + (size_t)(vr+8)*DH + kc) = r2;
        }
    }
}

extern "C" void kernel_launch(void* const* d_in, const int* in_sizes, int n_in,
                              void* d_out, int out_size) {
    const float* Q = (const float*)d_in[0];
    const float* K = (const float*)d_in[1];
    const float* V = (const float*)d_in[2];
    float* out = (float*)d_out;
    int batch = in_sizes[1] / (SEQ * DH);
    prep_kernel<<<dim3(SEQ/32, DH/32, batch), dim3(32,8)>>>(K, V);
    cudaFuncSetAttribute(jac_tc, cudaFuncAttributeMaxDynamicSharedMemorySize, DSMEM);
    jac_tc<<<dim3(NQ, batch), 256, DSMEM>>>(Q, K, out);
}